// round 14
// baseline (speedup 1.0000x reference)
#include <cuda_runtime.h>
#include <cuda_fp16.h>
#include <math.h>

#define NGROUPS   4
#define NPERG     10
#define NFILT     40
#define TIME_LEN  64000
#define BATCH     32
#define POOLSZ    401
#define POOLSTR   160
#define OUT_T     400
#define MAX_WS    512
#define MAX_KH    480            // kstr max (kpad<=464 + 8)
#define ROWS_B    256            // output rows per conv block (4 warps x 64)
#define PPB       8              // pooled outputs (p) per pool block

// Scratch (static device globals — allowed; runtime alloc is not)
__device__ __half g_kernh[NGROUPS][24 * MAX_KH];   // B: [channel][tap], fp16, zero-padded
__device__ float  g_win  [NGROUPS][MAX_WS * NPERG];
__device__ __half g_mid  [4ll * BATCH * TIME_LEN * NPERG];

struct MetaAll {
    int a[4], cs[4], ps[4], k[4], ws[4], Tg[4], kpad[4], kstr[4];
    long long off[4];
};

// ---------------------------------------------------------------------------
// Precompute: B table fp16 [n][tap] (n = 2f + (0:cos,1:sin), padded to 24 ch,
// kstr taps) + fp32 pooling windows. Double precision trig.
// ---------------------------------------------------------------------------
__global__ void precompute_kernel(const float* __restrict__ cf_in,
                                  const float* __restrict__ bw_in,
                                  const float* __restrict__ pw_in,
                                  MetaAll meta) {
    const int g  = blockIdx.x;
    const int a  = meta.a[g];
    const int k  = meta.k[g];
    const int h  = k >> 1;
    const int ws = meta.ws[g];
    const int cs = meta.cs[g];
    const int kstr = meta.kstr[g];
    const double PI = 3.14159265358979323846;
    const double Zd = sqrt(2.0 * log(2.0)) / PI;

    const int stride = blockDim.x * gridDim.y;
    const int start0 = blockIdx.y * blockDim.x + threadIdx.x;

    for (int idx = start0; idx < 24 * kstr; idx += stride) {
        int n = idx / kstr, tt = idx % kstr;
        double v = 0.0;
        if (n < 20 && tt < k) {
            int f = n >> 1;
            bool is_sin = n & 1;
            float cff = fminf(fmaxf(cf_in[a + f], 0.f), (float)PI);
            float bwf = fminf(fmaxf(bw_in[a + f], (float)(2.0 * Zd)), (float)(401.0 * Zd));
            double t  = (double)(tt - h);
            double bw = (double)bwf;
            double gauss = exp(-t * t / (2.0 * bw * bw));
            double norm  = 1.0 / (sqrt(2.0 * PI) * bw);
            double ph    = t * (double)cff;
            v = norm * gauss * (is_sin ? sin(ph) : cos(ph));
        }
        g_kernh[g][n * kstr + tt] = __float2half_rn((float)v);
    }
    for (int idx = start0; idx < ws * 10; idx += stride) {
        int j = idx / 10, f = idx % 10;
        float pwf = fminf(fmaxf(pw_in[a + f], (float)(2.0 / 401.0)), 0.5f);
        double sigma = (double)pwf / (double)cs * 401.0 / (double)ws;
        double hw = 0.5 * (double)(ws - 1);
        double u  = ((double)j - hw) / (sigma * hw);
        g_win[g][idx] = (float)exp(-0.5 * u * u);
    }
}

// ---------------------------------------------------------------------------
// mma.sync m16n8k16 fp16 -> fp32 (HMMA)
// ---------------------------------------------------------------------------
__device__ __forceinline__ void mma16816(float* d,
        unsigned a0, unsigned a1, unsigned a2, unsigned a3,
        unsigned b0, unsigned b1) {
    asm("mma.sync.aligned.m16n8k16.row.col.f32.f16.f16.f32 "
        "{%0,%1,%2,%3}, {%4,%5,%6,%7}, {%8,%9}, {%0,%1,%2,%3};"
        : "+f"(d[0]), "+f"(d[1]), "+f"(d[2]), "+f"(d[3])
        : "r"(a0), "r"(a1), "r"(a2), "r"(a3), "r"(b0), "r"(b1));
}

// ---------------------------------------------------------------------------
// Conv as im2col GEMM (R12 proven scheme): 128 threads / 4 warps, each warp
// owns 4 m16 tiles (64 rows) -> B fragment loads amortized 4x.
// ---------------------------------------------------------------------------
template<int CS>
__global__ void __launch_bounds__(128) convmma(
        const float* __restrict__ x, int g, long long off,
        int k, int kpad, int kstr, int Tg) {
    extern __shared__ __align__(16) __half smh[];
    __half* Bsh = smh;                       // 24*kstr halves
    const int nx = ROWS_B * CS + kpad;
    __half* xsh  = Bsh + 24 * kstr;          // nx+2 halves
    __half* xsh2 = xsh + nx + 2;             // odd-CS shifted copy

    const int tid = threadIdx.x;
    {   // stage B table as u32
        const unsigned* s = (const unsigned*)&g_kernh[g][0];
        unsigned* dst = (unsigned*)Bsh;
        const int n32 = 24 * kstr / 2;
        for (int i = tid; i < n32; i += 128) dst[i] = s[i];
    }
    const int w0 = blockIdx.x * ROWS_B;
    const int b  = blockIdx.y;
    const int h  = k >> 1;
    const int base = w0 * CS - h;
    const float* xb = x + (long long)b * TIME_LEN;
    for (int i = tid; i < nx; i += 128) {
        int gx = base + i;
        xsh[i] = __float2half_rn(((unsigned)gx < (unsigned)TIME_LEN) ? xb[gx] : 0.f);
        if (CS & 1) {
            int gx2 = gx + 1;
            xsh2[i] = __float2half_rn(((unsigned)gx2 < (unsigned)TIME_LEN) ? xb[gx2] : 0.f);
        }
    }
    __syncthreads();

    const int wid = tid >> 5, l = tid & 31, gq = l >> 2, t4 = l & 3;
    const int cb = 2 * t4;

    const __half* qr[8];
#pragma unroll
    for (int mt = 0; mt < 4; ++mt) {
#pragma unroll
        for (int jj = 0; jj < 2; ++jj) {
            int r = wid * 64 + mt * 16 + gq + jj * 8;
            int o = r * CS;
            if ((CS & 1) && (o & 1)) qr[mt * 2 + jj] = xsh2 + (o - 1);
            else                     qr[mt * 2 + jj] = xsh + o;
        }
    }
    const __half* q0 = Bsh + gq * kstr;
    const __half* q1 = Bsh + (8  + gq) * kstr;
    const __half* q2 = Bsh + (16 + gq) * kstr;

    float d[4][3][4];
#pragma unroll
    for (int mt = 0; mt < 4; ++mt)
#pragma unroll
        for (int n = 0; n < 3; ++n)
#pragma unroll
            for (int e = 0; e < 4; ++e) d[mt][n][e] = 0.f;

    for (int kk = 0; kk < kpad; kk += 16) {
        const int o = kk + cb;
        unsigned b00 = *(const unsigned*)(q0 + o), b01 = *(const unsigned*)(q0 + o + 8);
        unsigned b10 = *(const unsigned*)(q1 + o), b11 = *(const unsigned*)(q1 + o + 8);
        unsigned b20 = *(const unsigned*)(q2 + o), b21 = *(const unsigned*)(q2 + o + 8);
#pragma unroll
        for (int mt = 0; mt < 4; ++mt) {
            unsigned a0 = *(const unsigned*)(qr[mt * 2 + 0] + o);
            unsigned a1 = *(const unsigned*)(qr[mt * 2 + 1] + o);
            unsigned a2 = *(const unsigned*)(qr[mt * 2 + 0] + o + 8);
            unsigned a3 = *(const unsigned*)(qr[mt * 2 + 1] + o + 8);
            mma16816(d[mt][0], a0, a1, a2, a3, b00, b01);
            mma16816(d[mt][1], a0, a1, a2, a3, b10, b11);
            mma16816(d[mt][2], a0, a1, a2, a3, b20, b21);
        }
    }

    __half* mid = g_mid + off;
    const long long rowbase = (long long)b * Tg + w0;
#pragma unroll
    for (int mt = 0; mt < 4; ++mt) {
        int ra = wid * 64 + mt * 16 + gq;
        int rb = ra + 8;
#pragma unroll
        for (int n = 0; n < 3; ++n) {
            int p = n * 4 + t4;
            if (p < 10) {
                float v0 = d[mt][n][0] * d[mt][n][0] + d[mt][n][1] * d[mt][n][1];
                float v1 = d[mt][n][2] * d[mt][n][2] + d[mt][n][3] * d[mt][n][3];
                if (w0 + ra < Tg)
                    mid[(rowbase + ra) * 10 + p] = __float2half_rn(v0);
                if (w0 + rb < Tg)
                    mid[(rowbase + rb) * 10 + p] = __float2half_rn(v1);
            }
        }
    }
}

// ---------------------------------------------------------------------------
// Shared-staged depthwise Gaussian pooling.
// Block = 256 thr = 8 warps = 8 consecutive p of one (b, group).
// The union of the 8 windows ((PPB-1)*ps + ws rows) is staged to shared with
// coalesced u32 loads (each mid element read once per block), then warps
// compute from shared (lane stride 5 banks -> conflict-free).
// ---------------------------------------------------------------------------
__global__ void __launch_bounds__(256) pool_kernel(float* __restrict__ out, MetaAll m) {
    const int g = blockIdx.y;
    const int ws = m.ws[g], ps = m.ps[g], Tg = m.Tg[g], a = m.a[g];
    const long long off = m.off[g];
    const int span = (PPB - 1) * ps + ws;

    extern __shared__ __align__(8) char smraw[];
    float*  swin = (float*)smraw;                  // ws*10 fp32
    __half* smid = (__half*)(swin + ws * 10);      // span*10 fp16

    const int tid = threadIdx.x;
    const float* wg = g_win[g];
    for (int i = tid; i < ws * 10; i += 256) swin[i] = wg[i];

    const int nb_per_b = OUT_T / PPB;              // 50
    const int b  = blockIdx.x / nb_per_b;
    const int p0 = (blockIdx.x % nb_per_b) * PPB;
    const int t0 = p0 * ps - ws / 2;

    // stage union rows [t0, t0+span); zeros outside [0, Tg)
    const __half* mrow = g_mid + off + (long long)b * Tg * 10;
    unsigned* dmid = (unsigned*)smid;
    const int n32 = span * 5;
    for (int i = tid; i < n32; i += 256) {
        int t = t0 + i / 5;
        unsigned v = 0u;
        if ((unsigned)t < (unsigned)Tg)
            v = *(const unsigned*)(mrow + (long long)t * 10 + (i % 5) * 2);
        dmid[i] = v;
    }
    __syncthreads();

    const int w = tid >> 5, lane = tid & 31;
    const __half* mybase = smid + w * ps * 10;

    float2 acc2[5];
#pragma unroll
    for (int q = 0; q < 5; ++q) acc2[q] = make_float2(0.f, 0.f);

    for (int j = lane; j < ws; j += 32) {
        const __half2* row = (const __half2*)(mybase + j * 10);
        const float2* wr  = (const float2*)(swin + j * 10);
#pragma unroll
        for (int q = 0; q < 5; ++q) {
            float2 rv = __half22float2(row[q]);
            float2 wv = wr[q];
            acc2[q].x = fmaf(wv.x, rv.x, acc2[q].x);
            acc2[q].y = fmaf(wv.y, rv.y, acc2[q].y);
        }
    }

#pragma unroll
    for (int o = 16; o; o >>= 1)
#pragma unroll
        for (int q = 0; q < 5; ++q) {
            acc2[q].x += __shfl_down_sync(0xffffffffu, acc2[q].x, o);
            acc2[q].y += __shfl_down_sync(0xffffffffu, acc2[q].y, o);
        }

    if (lane == 0) {
        float* op = out + ((long long)b * OUT_T + p0 + w) * 40 + a;
#pragma unroll
        for (int q = 0; q < 5; ++q) {
            op[2*q]     = acc2[q].x;
            op[2*q + 1] = acc2[q].y;
        }
    }
}

// ---------------------------------------------------------------------------
// Host: replicate _mel_gabor_init + _group_meta exactly.
// ---------------------------------------------------------------------------
static void build_meta(MetaAll& m) {
    const double PI = 3.14159265358979323846;
    double freqs[257];
    for (int i = 0; i < 257; ++i) freqs[i] = 8000.0 * (double)i / 256.0;
    auto hz2mel = [](double f) { return 2595.0 * log10(1.0 + f / 700.0); };
    auto mel2hz = [](double mm) { return 700.0 * (pow(10.0, mm / 2595.0) - 1.0); };
    double mlo = hz2mel(60.0), mhi = hz2mel(7800.0);
    double hz[42];
    for (int i = 0; i < 42; ++i) hz[i] = mel2hz(mlo + (mhi - mlo) * (double)i / 41.0);

    const double Zd = sqrt(2.0 * log(2.0)) / PI;
    float cff[NFILT], bwf[NFILT];
    for (int i = 0; i < NFILT; ++i) {
        double l = hz[i], c = hz[i + 1], r = hz[i + 2];
        double peak = -1.0; int cb = 0;
        double vals[257];
        for (int j = 0; j < 257; ++j) {
            double v = (freqs[j] - l) / (c - l);
            double v2 = (r - freqs[j]) / (r - c);
            if (v2 < v) v = v2;
            if (v < 0.0) v = 0.0;
            vals[j] = sqrt(v);
            if (vals[j] > peak) { peak = vals[j]; cb = j; }
        }
        int fwhm = 0;
        for (int j = 0; j < 257; ++j) if (vals[j] >= 0.5 * peak) fwhm++;
        float cfv = (float)((double)cb * 2.0 * PI / 512.0);
        float bwv = (float)(sqrt(2.0 * log(2.0)) * 512.0 / (PI * (double)fwhm));
        cfv = fminf(fmaxf(cfv, 0.f), (float)PI);
        bwv = fminf(fmaxf(bwv, (float)(2.0 * Zd)), (float)(401.0 * Zd));
        cff[i] = cfv; bwf[i] = bwv;
    }

    const int divs[12] = {1, 2, 4, 5, 8, 10, 16, 20, 32, 40, 80, 160};
    long long off = 0;
    for (int g = 0; g < NGROUPS; ++g) {
        int a = g * NPERG, b = a + NPERG;
        float cmax = -1.f, bmax = -1.f;
        for (int i = a; i < b; ++i) {
            if (cff[i] > cmax) cmax = cff[i];
            if (bwf[i] > bmax) bmax = bwf[i];
        }
        double s = PI / (double)cmax;          // STRIDE_FACTOR = 1
        if (s < 1.0) s = 1.0;
        int cs = 1;
        for (int d = 0; d < 12; ++d) if ((double)divs[d] <= s) cs = divs[d];
        int k = (int)((double)bmax * 3.0);
        k += 1 - (k % 2);
        int ws = (int)(401.0 / (double)cs + 0.5);
        ws += 1 - (ws % 2);
        if (ws > MAX_WS - 1) ws = MAX_WS - 1;
        m.a[g] = a; m.cs[g] = cs; m.ps[g] = POOLSTR / cs;
        m.k[g] = k; m.ws[g] = ws; m.Tg[g] = TIME_LEN / cs;
        m.kpad[g] = ((k + 15) / 16) * 16;
        m.kstr[g] = m.kpad[g] + 8;             // bank-spread row stride
        m.off[g] = off;
        off += (long long)BATCH * (TIME_LEN / cs) * NPERG;
    }
}

template<int CS>
static void launch_conv(const float* x, int g, const MetaAll& m) {
    int nx = ROWS_B * CS + m.kpad[g];
    size_t smem = (size_t)(24 * m.kstr[g] + (nx + 2) * ((CS & 1) ? 2 : 1))
                  * sizeof(__half);
    cudaFuncSetAttribute(convmma<CS>, cudaFuncAttributeMaxDynamicSharedMemorySize,
                         (int)smem);
    dim3 grid((m.Tg[g] + ROWS_B - 1) / ROWS_B, BATCH);
    convmma<CS><<<grid, 128, smem>>>(x, g, m.off[g], m.k[g], m.kpad[g],
                                     m.kstr[g], m.Tg[g]);
}

extern "C" void kernel_launch(void* const* d_in, const int* in_sizes, int n_in,
                              void* d_out, int out_size) {
    const float* x  = (const float*)d_in[0];
    const float* cf = (const float*)d_in[1];
    const float* bw = (const float*)d_in[2];
    const float* pw = (const float*)d_in[3];
    float* out = (float*)d_out;

    MetaAll m;
    build_meta(m);

    precompute_kernel<<<dim3(NGROUPS, 8), 256>>>(cf, bw, pw, m);

    for (int g = 0; g < NGROUPS; ++g) {
        switch (m.cs[g]) {
            case 1:  launch_conv<1 >(x, g, m); break;
            case 2:  launch_conv<2 >(x, g, m); break;
            case 4:  launch_conv<4 >(x, g, m); break;
            case 5:  launch_conv<5 >(x, g, m); break;
            case 8:  launch_conv<8 >(x, g, m); break;
            case 10: launch_conv<10>(x, g, m); break;
            case 16: launch_conv<16>(x, g, m); break;
            case 20: launch_conv<20>(x, g, m); break;
            case 32: launch_conv<32>(x, g, m); break;
            default: launch_conv<40>(x, g, m); break;
        }
    }

    size_t pool_smem = 0;
    for (int g = 0; g < NGROUPS; ++g) {
        int span = (PPB - 1) * m.ps[g] + m.ws[g];
        size_t s = (size_t)(m.ws[g] * NPERG) * sizeof(float)
                 + (size_t)(span * NPERG) * sizeof(__half);
        if (s > pool_smem) pool_smem = s;
    }
    dim3 pool_grid(BATCH * (OUT_T / PPB), NGROUPS);
    pool_kernel<<<pool_grid, 256, pool_smem>>>(out, m);
}